// round 14
// baseline (speedup 1.0000x reference)
#include <cuda_runtime.h>
#include <cuda_bf16.h>

// ChamferLoss, B=4, N=M=8192, 3D. Two kernels (grid barrier impossible at this
// register pressure — R13 post-mortem).
// Pair kernel: R10 config (THREADS=128, IPT=16, JT=64) at the fp32 wide-fma
// floor (~55us). Packed f32x2, REDUX.MIN.s32 col reduction.
// R14: partials stored as bf16 (10MB -> 5MB) -> reduce LSU work halves.
// Precision: +-2^-9 rel per partial, averages to ~1e-5 on the final mean.

#define BB 4
#define NPTS 8192
#define MPTS 8192
#define THREADS 128
#define IPT 16
#define KKN (IPT / 2)
#define ITILES (NPTS / (THREADS * IPT))   // 4
#define JT 64
#define JCH (MPTS / JT)                   // 128
#define G 8
#define CSLABS (ITILES * 4)               // 16 col slabs
#define SLABU4 (BB * NPTS / 8)            // 4096 uint4 (8 bf16 each) per slab

typedef unsigned long long u64;

__device__ __nv_bfloat16 g_p1[JT][BB * NPTS];      // row-min partials (4 MB)
__device__ __nv_bfloat16 g_p2[CSLABS][BB * MPTS];  // col-min partials (1 MB)

#define PACK2(o, lo, hi)   asm("mov.b64 %0,{%1,%2};" : "=l"(o) : "f"(lo), "f"(hi))
#define UNPACK2(lo, hi, i) asm("mov.b64 {%0,%1},%2;" : "=f"(lo), "=f"(hi) : "l"(i))
#define FMA2(d, a, b, c)   asm("fma.rn.f32x2 %0,%1,%2,%3;" : "=l"(d) : "l"(a), "l"(b), "l"(c))
#define ADD2(d, a, b)      asm("add.rn.f32x2 %0,%1,%2;" : "=l"(d) : "l"(a), "l"(b))

__device__ __forceinline__ unsigned umin2(unsigned a, unsigned b) {
    __nv_bfloat162 x = *reinterpret_cast<__nv_bfloat162*>(&a);
    __nv_bfloat162 y = *reinterpret_cast<__nv_bfloat162*>(&b);
    __nv_bfloat162 r = __hmin2(x, y);
    return *reinterpret_cast<unsigned*>(&r);
}
__device__ __forceinline__ float usum2(unsigned a) {
    __nv_bfloat162 x = *reinterpret_cast<__nv_bfloat162*>(&a);
    return __low2float(x) + __high2float(x);
}

__global__ void __launch_bounds__(THREADS) chamfer_fused_kernel(
    const float* __restrict__ xyz1, const float* __restrict__ xyz2, float* __restrict__ out)
{
    __shared__ ulonglong2 tA[JCH];
    __shared__ ulonglong2 tB[JCH];

    const int tid = threadIdx.x;
    const int lane = tid & 31;
    const int warp = tid >> 5;
    const int b = blockIdx.z;
    const int iBase = blockIdx.x * (THREADS * IPT);
    const int jBase = blockIdx.y * JCH;
    const float* __restrict__ P = xyz1 + (size_t)b * NPTS * 3;
    const float* __restrict__ Q = xyz2 + (size_t)b * MPTS * 3;

    if (blockIdx.x == 0 && blockIdx.y == 0 && blockIdx.z == 0 && tid == 0)
        out[0] = 0.f;

    u64 ax2[KKN], ay2[KKN], az2[KKN], n12[KKN];
    float mn[IPT];
#pragma unroll
    for (int kk = 0; kk < KKN; kk++) {
        int i0 = iBase + tid + (2 * kk) * THREADS;
        int i1 = iBase + tid + (2 * kk + 1) * THREADS;
        float x0 = P[i0 * 3], y0 = P[i0 * 3 + 1], z0 = P[i0 * 3 + 2];
        float x1 = P[i1 * 3], y1 = P[i1 * 3 + 1], z1 = P[i1 * 3 + 2];
        PACK2(ax2[kk], x0, x1);
        PACK2(ay2[kk], y0, y1);
        PACK2(az2[kk], z0, z1);
        float n0 = fmaf(x0, x0, fmaf(y0, y0, z0 * z0));
        float n1 = fmaf(x1, x1, fmaf(y1, y1, z1 * z1));
        PACK2(n12[kk], n0, n1);
        mn[2 * kk] = 3.4e38f;
        mn[2 * kk + 1] = 3.4e38f;
    }

    for (int jj = tid; jj < JCH; jj += THREADS) {
        int j = jBase + jj;
        float x = Q[j * 3], y = Q[j * 3 + 1], z = Q[j * 3 + 2];
        float n2 = fmaf(x, x, fmaf(y, y, z * z));
        float nx = -2.f * x, ny = -2.f * y, nz = -2.f * z;
        u64 X2, Y2, Z2, W2;
        PACK2(X2, nx, nx);
        PACK2(Y2, ny, ny);
        PACK2(Z2, nz, nz);
        PACK2(W2, n2, n2);
        tA[jj] = make_ulonglong2(X2, Y2);
        tB[jj] = make_ulonglong2(Z2, W2);
    }
    __syncthreads();

    __nv_bfloat16* __restrict__ colOut = g_p2[blockIdx.x * 4 + warp] + b * MPTS + jBase;

    for (int jj0 = 0; jj0 < JCH; jj0 += G) {
        int cvi[G];
#pragma unroll
        for (int g = 0; g < G; g++) {
            ulonglong2 ba = tA[jj0 + g];
            ulonglong2 bb = tB[jj0 + g];
            float c0 = 3.4e38f, c1 = 3.4e38f;
#pragma unroll
            for (int kk = 0; kk < KKN; kk++) {
                u64 w, t;
                ADD2(w, n12[kk], bb.y);        // n1 + n2
                FMA2(t, bb.x, az2[kk], w);     // += -2z*az
                FMA2(t, ba.y, ay2[kk], t);     // += -2y*ay
                FMA2(t, ba.x, ax2[kk], t);     // += -2x*ax -> dist^2 x2
                float t0, t1;
                UNPACK2(t0, t1, t);
                mn[2 * kk]     = fminf(mn[2 * kk], t0);
                mn[2 * kk + 1] = fminf(mn[2 * kk + 1], t1);
                c0 = fminf(c0, t0);
                c1 = fminf(c1, t1);
            }
            cvi[g] = __float_as_int(fmaxf(fminf(c0, c1), 0.f));  // clamp -> s32 order
        }
#pragma unroll
        for (int g = 0; g < G; g++)
            cvi[g] = __reduce_min_sync(0xffffffffu, cvi[g]);
        int myv = cvi[0];
#pragma unroll
        for (int g = 1; g < G; g++)
            if (lane == g) myv = cvi[g];
        if (lane < G)
            colOut[jj0 + lane] = __float2bfloat16(__int_as_float(myv));
    }

    __nv_bfloat16* __restrict__ rowOut = g_p1[blockIdx.y] + b * NPTS;
#pragma unroll
    for (int kk = 0; kk < KKN; kk++) {
        int i0 = iBase + tid + (2 * kk) * THREADS;
        int i1 = iBase + tid + (2 * kk + 1) * THREADS;
        rowOut[i0] = __float2bfloat16(mn[2 * kk]);
        rowOut[i1] = __float2bfloat16(mn[2 * kk + 1]);
    }
}

// Reduce: 512 blocks x 128 threads. Blocks 0..255 rows, 256..511 cols.
// Block covers 16 uint4-columns (each = 8 bf16 elements).
// share = warp*2 + (lane>>4) in 0..7: rows scan 8 slabs, cols scan 2.
// Packed __hmin2 mins; shfl_xor(16) + smem combine; one atomicAdd per block.
__global__ void chamfer_reduce_kernel(float* __restrict__ out) {
    __shared__ uint4 smr[4][16];
    const int lane = threadIdx.x & 31;
    const int warp = threadIdx.x >> 5;
    const int c = lane & 15;
    const int share = warp * 2 + (lane >> 4);  // 0..7
    const bool isRow = blockIdx.x < 256;
    const int blkLocal = isRow ? blockIdx.x : blockIdx.x - 256;

    unsigned a0, a1, a2, a3;
    if (isRow) {
        const uint4* base = (const uint4*)g_p1[0] + blkLocal * 16 + c;
        uint4 v = base[(size_t)(share * 8) * SLABU4];
        a0 = v.x; a1 = v.y; a2 = v.z; a3 = v.w;
#pragma unroll
        for (int s = 1; s < 8; s++) {
            uint4 w = base[(size_t)(share * 8 + s) * SLABU4];
            a0 = umin2(a0, w.x); a1 = umin2(a1, w.y);
            a2 = umin2(a2, w.z); a3 = umin2(a3, w.w);
        }
    } else {
        const uint4* base = (const uint4*)g_p2[0] + blkLocal * 16 + c;
        uint4 v = base[(size_t)(share * 2) * SLABU4];
        uint4 w = base[(size_t)(share * 2 + 1) * SLABU4];
        a0 = umin2(v.x, w.x); a1 = umin2(v.y, w.y);
        a2 = umin2(v.z, w.z); a3 = umin2(v.w, w.w);
    }
    // combine the two half-warp shares
    a0 = umin2(a0, __shfl_xor_sync(0xffffffffu, a0, 16));
    a1 = umin2(a1, __shfl_xor_sync(0xffffffffu, a1, 16));
    a2 = umin2(a2, __shfl_xor_sync(0xffffffffu, a2, 16));
    a3 = umin2(a3, __shfl_xor_sync(0xffffffffu, a3, 16));
    if (lane < 16) smr[warp][c] = make_uint4(a0, a1, a2, a3);
    __syncthreads();

    if (warp == 0 && lane < 16) {
        uint4 r = smr[0][c];
#pragma unroll
        for (int w = 1; w < 4; w++) {
            uint4 v = smr[w][c];
            r.x = umin2(r.x, v.x); r.y = umin2(r.y, v.y);
            r.z = umin2(r.z, v.z); r.w = umin2(r.w, v.w);
        }
        float s = ((usum2(r.x) + usum2(r.y)) + (usum2(r.z) + usum2(r.w)))
                  * (1.f / (BB * NPTS));
#pragma unroll
        for (int o = 8; o > 0; o >>= 1)
            s += __shfl_down_sync(0xffffu, s, o);
        if (lane == 0) atomicAdd(out, s);
    }
}

extern "C" void kernel_launch(void* const* d_in, const int* in_sizes, int n_in,
                              void* d_out, int out_size) {
    const float* xyz1 = (const float*)d_in[0];
    const float* xyz2 = (const float*)d_in[1];
    float* out = (float*)d_out;

    dim3 grid(ITILES, JT, BB);  // (4, 64, 4) = 1024 blocks
    chamfer_fused_kernel<<<grid, THREADS>>>(xyz1, xyz2, out);

    chamfer_reduce_kernel<<<512, 128>>>(out);
}